// round 8
// baseline (speedup 1.0000x reference)
#include <cuda_runtime.h>

#define N_SAMP 8000
#define T_DIM  64
#define F_DIM  64
#define NCOL   320   // 40 time steps * 8 features
#define W127   91440 // 127*144*5

// 10.24 MB scratch for ranks: layout [n][t*8+e]
__device__ float g_rank[(size_t)N_SAMP * NCOL];

__device__ __forceinline__ unsigned desc_key(float v){
    unsigned b = __float_as_uint(v);
    unsigned u = b ^ ((b & 0x80000000u) ? 0xFFFFFFFFu : 0x80000000u); // ascending order key
    return ~u;                                                        // descending order key
}

// ---------------------------------------------------------------------------
// Kernel 1: exact descending rank (stable, index tie-break) per (t,e) column
// over all 8000 samples. One block per column, 1024 threads.
// Shared: du[8192] u32 | hist[16384] u32 | order[8192] u16  = 114688 B
// ---------------------------------------------------------------------------
__global__ __launch_bounds__(1024) void rank_kernel(const float* __restrict__ x){
    extern __shared__ char sm[];
    unsigned*       du    = (unsigned*)sm;               // 8192
    unsigned*       hist  = du + 8192;                   // 16384
    unsigned short* order = (unsigned short*)(hist + 16384); // 8192
    __shared__ unsigned wsum[32];

    const int col = blockIdx.x;
    const int tt  = col >> 3;
    const int e   = col & 7;
    const int tid = threadIdx.x;
    const float* xp = x + (size_t)(24 + tt) * F_DIM + e;

    #pragma unroll
    for (int i = tid; i < 8192; i += 1024){
        unsigned d = 0xFFFFFFFFu;                        // padding sorts last
        if (i < N_SAMP) d = desc_key(__ldg(xp + (size_t)i * (T_DIM * F_DIM)));
        du[i] = d;
    }
    #pragma unroll
    for (int i = tid; i < 16384; i += 1024) hist[i] = 0u;
    __syncthreads();

    #pragma unroll
    for (int i = tid; i < 8192; i += 1024) atomicAdd(&hist[du[i] >> 18], 1u);
    __syncthreads();

    // exclusive scan over 16384 bins: each thread owns 16 consecutive bins
    unsigned local[16];
    unsigned s = 0;
    const int b0 = tid * 16;
    #pragma unroll
    for (int j = 0; j < 16; j++){ local[j] = hist[b0 + j]; s += local[j]; }
    const unsigned lane = tid & 31, wid = tid >> 5;
    unsigned inc = s;
    #pragma unroll
    for (int off = 1; off < 32; off <<= 1){
        unsigned o = __shfl_up_sync(0xffffffffu, inc, off);
        if (lane >= off) inc += o;
    }
    if (lane == 31) wsum[wid] = inc;
    __syncthreads();
    if (wid == 0){
        unsigned vv = wsum[lane], ii = vv;
        #pragma unroll
        for (int off = 1; off < 32; off <<= 1){
            unsigned o = __shfl_up_sync(0xffffffffu, ii, off);
            if (lane >= off) ii += o;
        }
        wsum[lane] = ii - vv;                            // exclusive warp prefix
    }
    __syncthreads();
    unsigned run = wsum[wid] + (inc - s);                // exclusive thread prefix
    #pragma unroll
    for (int j = 0; j < 16; j++){ unsigned c = local[j]; hist[b0 + j] = run; run += c; }
    __syncthreads();

    // scatter element ids into bin-sorted order; afterwards hist[b] = end of bin b
    #pragma unroll
    for (int i = tid; i < 8192; i += 1024){
        unsigned b = du[i] >> 18;
        unsigned p = atomicAdd(&hist[b], 1u);
        order[p] = (unsigned short)i;
    }
    __syncthreads();

    // exact rank: base = #elements in smaller bins, + within-bin count with
    // (value, index) tie-break => matches stable argsort of -x.
    for (int p = tid; p < 8192; p += 1024){
        int i = order[p];
        if (i < N_SAMP){
            unsigned key   = du[i];
            unsigned b     = key >> 18;
            unsigned end   = hist[b];
            unsigned start = b ? hist[b - 1] : 0u;
            int cnt = 0;
            for (unsigned q = start; q < end; q++){
                int m = order[q];
                unsigned km = du[m];
                cnt += (km < key) || (km == key && m < i);
            }
            g_rank[(size_t)i * NCOL + col] = (float)((int)start + cnt) * (1.0f / 8000.0f);
        }
    }
}

// ---------------------------------------------------------------------------
// Kernel 2: fused window-stats + single-channel conv + leaky-relu + linear.
// Warp per sample, 4 warps / 128 threads per block, dynamic shared.
// ---------------------------------------------------------------------------
__device__ __forceinline__ void ffma2(unsigned long long &d, unsigned long long a, unsigned long long b){
    asm("fma.rn.f32x2 %0, %1, %2, %0;" : "+l"(d) : "l"(a), "l"(b));
}
__device__ __forceinline__ float2 upk2(unsigned long long v){
    float2 f; asm("mov.b64 {%0, %1}, %2;" : "=f"(f.x), "=f"(f.y) : "l"(v)); return f;
}

__global__ __launch_bounds__(128) void main_kernel(
    const float* __restrict__ x, const float* __restrict__ conv_w,
    const float* __restrict__ conv_b, const float* __restrict__ lin_w,
    const float* __restrict__ lin_b, float* __restrict__ out)
{
    extern __shared__ char sm[];
    float* xrowAll = (float*)sm;              // 4 * 40 * 68
    float* xeAll   = xrowAll + 4 * 40 * 68;   // 4 * 64 * 8
    float* dAll    = xeAll   + 4 * 64 * 8;    // 4 * 200
    float* wTs     = dAll    + 4 * 200;       // 720  (wTs[k*144 + c])
    float* linWs   = wTs + 720;               // 36
    float* miscS   = linWs + 36;              // 2

    const int tid  = threadIdx.x;
    const int lane = tid & 31;
    const int w    = tid >> 5;

    // transpose the single live conv filter: wTs[k][c] = conv_w[127][c][k]
    for (int idx = tid; idx < 720; idx += 128){
        int k = idx / 144, c = idx - k * 144;
        wTs[idx] = conv_w[W127 + c * 5 + k];
    }
    if (tid < 36) linWs[tid] = lin_w[tid];
    if (tid == 0){ miscS[0] = conv_b[127]; miscS[1] = lin_b[0]; }
    __syncthreads();

    const int n = blockIdx.x * 4 + w;         // grid = 2000 -> exactly 8000
    float* xrowW = xrowAll + w * (40 * 68);
    float* xeW   = xeAll   + w * (64 * 8);
    float* dW    = dAll    + w * 200;
    const float* xs = x + (size_t)n * (T_DIM * F_DIM);

    // stage rows 24..63, all 64 channels (coalesced, padded stride 68)
    #pragma unroll
    for (int it = 0; it < 20; it++){
        int f4   = it * 32 + lane;
        int flat = f4 * 4;
        int row  = flat >> 6, cc = flat & 63;
        *(float4*)(xrowW + row * 68 + cc) = *(const float4*)(xs + 1536 + flat);
    }
    // stage rows 0..63, first 8 features (for window stats)
    #pragma unroll
    for (int it = 0; it < 4; it++){
        int q = it * 32 + lane;
        int row = q >> 1, half = q & 1;
        *(float4*)(xeW + row * 8 + half * 4) = *(const float4*)(xs + row * 64 + half * 4);
    }
    __syncwarp();

    const float convB = miscS[0], linB = miscS[1];

    #pragma unroll 1
    for (int r = 0; r < 2; r++){
        const int t = lane + r * 32;
        if (t < 40){
            const float4* xe4 = (const float4*)xeW;

            // 20-window: rows 5+t .. 24+t
            float s20[8], q20[8], mx20[8], mn20[8];
            #pragma unroll
            for (int e2 = 0; e2 < 8; e2++){ s20[e2]=0.f; q20[e2]=0.f; mx20[e2]=-3.4e38f; mn20[e2]=3.4e38f; }
            #pragma unroll
            for (int j = 0; j < 20; j++){
                float4 a = xe4[(5 + t + j) * 2];
                float4 b = xe4[(5 + t + j) * 2 + 1];
                float v[8] = {a.x, a.y, a.z, a.w, b.x, b.y, b.z, b.w};
                #pragma unroll
                for (int e2 = 0; e2 < 8; e2++){
                    float vv = v[e2];
                    s20[e2] += vv;
                    q20[e2]  = fmaf(vv, vv, q20[e2]);
                    mx20[e2] = fmaxf(mx20[e2], vv);
                    mn20[e2] = fminf(mn20[e2], vv);
                }
            }
            // 5-window: rows 20+t .. 24+t
            float s5[8], q5[8], mx5[8], mn5[8];
            #pragma unroll
            for (int e2 = 0; e2 < 8; e2++){ s5[e2]=0.f; q5[e2]=0.f; mx5[e2]=-3.4e38f; mn5[e2]=3.4e38f; }
            #pragma unroll
            for (int j = 0; j < 5; j++){
                float4 a = xe4[(20 + t + j) * 2];
                float4 b = xe4[(20 + t + j) * 2 + 1];
                float v[8] = {a.x, a.y, a.z, a.w, b.x, b.y, b.z, b.w};
                #pragma unroll
                for (int e2 = 0; e2 < 8; e2++){
                    float vv = v[e2];
                    s5[e2] += vv;
                    q5[e2]  = fmaf(vv, vv, q5[e2]);
                    mx5[e2] = fmaxf(mx5[e2], vv);
                    mn5[e2] = fminf(mn5[e2], vv);
                }
            }
            float mean5[8], std5[8], mean20[8], std20[8];
            #pragma unroll
            for (int e2 = 0; e2 < 8; e2++){
                mean20[e2] = s20[e2] * 0.05f;
                std20[e2]  = sqrtf(fmaxf((q20[e2] - s20[e2]*s20[e2]*0.05f) * (1.0f/19.0f), 0.f));
                mean5[e2]  = s5[e2] * 0.2f;
                std5[e2]   = sqrtf(fmaxf((q5[e2] - s5[e2]*s5[e2]*0.2f) * 0.25f, 0.f));
            }
            // ranks (identical for week & month channel groups)
            const float4* rp = (const float4*)(g_rank + (size_t)n * NCOL + t * 8);
            float4 rka = rp[0], rkb = rp[1];
            float rk[8] = {rka.x, rka.y, rka.z, rka.w, rkb.x, rkb.y, rkb.z, rkb.w};

            // raw 64-channel dot via packed f32x2 FMA: d[k] += x[24+t, c] * w[c][k]
            unsigned long long dax[5], day[5];
            #pragma unroll
            for (int k = 0; k < 5; k++){ dax[k] = 0ULL; day[k] = 0ULL; }
            const ulonglong2* xr2 = (const ulonglong2*)(xrowW + t * 68);
            #pragma unroll
            for (int c4 = 0; c4 < 16; c4++){
                ulonglong2 xv = xr2[c4];
                #pragma unroll
                for (int k = 0; k < 5; k++){
                    ulonglong2 wv = *(const ulonglong2*)(wTs + k * 144 + c4 * 4);
                    ffma2(dax[k], xv.x, wv.x);
                    ffma2(day[k], xv.y, wv.y);
                }
            }
            // derived-channel contributions (channels 64..143)
            float dst[5] = {0.f, 0.f, 0.f, 0.f, 0.f};
            auto acc4 = [&](int cb, float v0, float v1, float v2, float v3){
                #pragma unroll
                for (int k = 0; k < 5; k++){
                    float4 wv = *(const float4*)(wTs + k * 144 + cb);
                    dst[k] = fmaf(v0, wv.x, fmaf(v1, wv.y, fmaf(v2, wv.z, fmaf(v3, wv.w, dst[k]))));
                }
            };
            acc4( 64, mean5[0], mean5[1], mean5[2], mean5[3]);
            acc4( 68, mean5[4], mean5[5], mean5[6], mean5[7]);
            acc4( 72, std5[0],  std5[1],  std5[2],  std5[3]);
            acc4( 76, std5[4],  std5[5],  std5[6],  std5[7]);
            acc4( 80, rk[0], rk[1], rk[2], rk[3]);
            acc4( 84, rk[4], rk[5], rk[6], rk[7]);
            acc4( 88, mx5[0], mx5[1], mx5[2], mx5[3]);
            acc4( 92, mx5[4], mx5[5], mx5[6], mx5[7]);
            acc4( 96, mn5[0], mn5[1], mn5[2], mn5[3]);
            acc4(100, mn5[4], mn5[5], mn5[6], mn5[7]);
            acc4(104, mean20[0], mean20[1], mean20[2], mean20[3]);
            acc4(108, mean20[4], mean20[5], mean20[6], mean20[7]);
            acc4(112, std20[0], std20[1], std20[2], std20[3]);
            acc4(116, std20[4], std20[5], std20[6], std20[7]);
            acc4(120, rk[0], rk[1], rk[2], rk[3]);
            acc4(124, rk[4], rk[5], rk[6], rk[7]);
            acc4(128, mx20[0], mx20[1], mx20[2], mx20[3]);
            acc4(132, mx20[4], mx20[5], mx20[6], mx20[7]);
            acc4(136, mn20[0], mn20[1], mn20[2], mn20[3]);
            acc4(140, mn20[4], mn20[5], mn20[6], mn20[7]);

            #pragma unroll
            for (int k = 0; k < 5; k++){
                float2 a1 = upk2(dax[k]), a2 = upk2(day[k]);
                dW[t * 5 + k] = dst[k] + ((a1.x + a1.y) + (a2.x + a2.y));
            }
        }
    }
    __syncwarp();

    // conv taps across t + bias + leaky relu + linear head, warp-reduced.
    // 36 output positions but 32 lanes: lane p handles position p, and
    // lanes 0..3 ALSO handle positions 32..35 (this was the round-5 bug).
    float c;
    {
        float h = convB;
        #pragma unroll
        for (int k = 0; k < 5; k++) h += dW[(lane + k) * 5 + k];
        h = (h >= 0.f) ? h : 0.01f * h;
        c = h * linWs[lane];
        if (lane < 4){
            float h2 = convB;
            #pragma unroll
            for (int k = 0; k < 5; k++) h2 += dW[(lane + 32 + k) * 5 + k];
            h2 = (h2 >= 0.f) ? h2 : 0.01f * h2;
            c = fmaf(h2, linWs[lane + 32], c);
        }
    }
    #pragma unroll
    for (int off = 16; off; off >>= 1) c += __shfl_down_sync(0xffffffffu, c, off);
    if (lane == 0) out[n] = c + linB;
}

// ---------------------------------------------------------------------------
extern "C" void kernel_launch(void* const* d_in, const int* in_sizes, int n_in,
                              void* d_out, int out_size)
{
    const float* x      = (const float*)d_in[0];
    const float* conv_w = (const float*)d_in[1];
    const float* conv_b = (const float*)d_in[2];
    const float* lin_w  = (const float*)d_in[3];
    const float* lin_b  = (const float*)d_in[4];
    float* out = (float*)d_out;

    cudaFuncSetAttribute(rank_kernel, cudaFuncAttributeMaxDynamicSharedMemorySize, 114688);
    cudaFuncSetAttribute(main_kernel, cudaFuncAttributeMaxDynamicSharedMemorySize, 57984);

    rank_kernel<<<NCOL, 1024, 114688>>>(x);
    main_kernel<<<N_SAMP / 4, 128, 57984>>>(x, conv_w, conv_b, lin_w, lin_b, out);
}